// round 5
// baseline (speedup 1.0000x reference)
#include <cuda_runtime.h>
#include <cuda_bf16.h>
#include <math.h>

// ---------------------------------------------------------------------------
// DiscriminativeLoss: B=4 batches, two losses:
//   binary:   pred [2, N], labels in [0,2)
//   instance: pred [5, N], labels in [0,6)
// out[0] = mean_b binary_loss, out[1] = mean_b instance_loss
//
// 2 kernels, each launched as ONE full wave (592 blocks = 148 SMs x 4),
// partitioned by byte-load ratio: 49 blocks/batch binary, 99 blocks/batch
// instance. Pass2 folds 1/cnt into the accumulation (single accumulator)
// and finalizes in its last block.
// ---------------------------------------------------------------------------

#define DELTA_V   0.5f
#define TWO_DD    6.0f     // 2 * delta_d
#define PREG      0.001f

#define NB_BIN    49
#define NB_INST   99
#define TOTAL_BLOCKS (4 * (NB_BIN + NB_INST))   // 592 = 148 SMs * 4 blocks

// Scratch (alloc-free rule: __device__ globals). Zero at load; the pass2
// last block re-zeros everything so graph replays are deterministic.
__device__ float    g_sum[2][4][8][8];   // [type][b][k][d]
__device__ float    g_cnt[2][4][8];      // [type][b][k]
__device__ float    g_var2[2][4];        // [type][b]  (inv-count-weighted)
__device__ unsigned g_done;

// Block -> (type, batch, xi, nblk) mapping
struct Work { int type, b, xi, nblk; };
__device__ __forceinline__ Work map_block(int bid) {
    Work w;
    if (bid < NB_BIN * 4) {
        w.type = 0; w.b = bid / NB_BIN; w.xi = bid % NB_BIN; w.nblk = NB_BIN;
    } else {
        int j = bid - NB_BIN * 4;
        w.type = 1; w.b = j / NB_INST; w.xi = j % NB_INST; w.nblk = NB_INST;
    }
    return w;
}

// ---------------------------------------------------------------------------
// Pass 1: segment sums + counts
// ---------------------------------------------------------------------------
template <int D, int K>
__device__ __forceinline__ void reduce_impl(const float* __restrict__ pred,
                                            const int* __restrict__ labels,
                                            int N, int xi, int nblk,
                                            float* __restrict__ gsum,
                                            float* __restrict__ gcnt) {
    float s[K * D];
    float c[K];
#pragma unroll
    for (int i = 0; i < K * D; i++) s[i] = 0.f;
#pragma unroll
    for (int k = 0; k < K; k++) c[k] = 0.f;

    const int n4 = N >> 2;
    const int4* lab4 = (const int4*)labels;
    const int stride = nblk * 256;

#pragma unroll 2
    for (int i = xi * 256 + threadIdx.x; i < n4; i += stride) {
        int4 L = lab4[i];
        float4 v[D];
#pragma unroll
        for (int d = 0; d < D; d++)
            v[d] = ((const float4*)(pred + (size_t)d * N))[i];

        int ls[4] = {L.x, L.y, L.z, L.w};
#pragma unroll
        for (int e = 0; e < 4; e++) {
            int lab = ls[e];
#pragma unroll
            for (int k = 0; k < K; k++) {
                float m = (lab == k) ? 1.f : 0.f;
                c[k] += m;
#pragma unroll
                for (int d = 0; d < D; d++) {
                    float val = (e == 0) ? v[d].x : (e == 1) ? v[d].y
                               : (e == 2) ? v[d].z : v[d].w;
                    s[k * D + d] += m * val;
                }
            }
        }
    }

#pragma unroll
    for (int o = 16; o > 0; o >>= 1) {
#pragma unroll
        for (int i = 0; i < K * D; i++) s[i] += __shfl_xor_sync(0xffffffffu, s[i], o);
#pragma unroll
        for (int k = 0; k < K; k++) c[k] += __shfl_xor_sync(0xffffffffu, c[k], o);
    }

    __shared__ float sh[K * D + K];
    for (int i = threadIdx.x; i < K * D + K; i += blockDim.x) sh[i] = 0.f;
    __syncthreads();
    if ((threadIdx.x & 31) == 0) {
#pragma unroll
        for (int i = 0; i < K * D; i++) atomicAdd(&sh[i], s[i]);
#pragma unroll
        for (int k = 0; k < K; k++) atomicAdd(&sh[K * D + k], c[k]);
    }
    __syncthreads();
    if (threadIdx.x < K * D) {
        int k = threadIdx.x / D, d = threadIdx.x % D;
        atomicAdd(&gsum[k * 8 + d], sh[threadIdx.x]);
    }
    if (threadIdx.x < K) atomicAdd(&gcnt[threadIdx.x], sh[K * D + threadIdx.x]);
}

__global__ __launch_bounds__(256, 4) void pass1_kernel(
    const float* __restrict__ binL, const int* __restrict__ binLab,
    const float* __restrict__ instL, const int* __restrict__ instLab, int N) {
    Work w = map_block(blockIdx.x);
    if (w.type == 0) {
        reduce_impl<2, 2>(binL + (size_t)w.b * 2 * N, binLab + (size_t)w.b * N,
                          N, w.xi, w.nblk, &g_sum[0][w.b][0][0], &g_cnt[0][w.b][0]);
    } else {
        reduce_impl<5, 6>(instL + (size_t)w.b * 5 * N, instLab + (size_t)w.b * N,
                          N, w.xi, w.nblk, &g_sum[1][w.b][0][0], &g_cnt[1][w.b][0]);
    }
}

// ---------------------------------------------------------------------------
// Pass 2: means+inv_cnt prologue, single-accumulator hinge variance,
// last-block finalize + scratch re-zero.
// ---------------------------------------------------------------------------
template <int D, int K>
__device__ __forceinline__ void var_impl(const float* __restrict__ pred,
                                         const int* __restrict__ labels,
                                         int N, int xi, int nblk,
                                         const float* __restrict__ gsum,
                                         const float* __restrict__ gcnt,
                                         float* __restrict__ gvar) {
    __shared__ float sm[K * D];      // segment means
    __shared__ float sinv[K];        // 1 / counts
    if (threadIdx.x < K * D) {
        int k = threadIdx.x / D, d = threadIdx.x % D;
        sm[threadIdx.x] = gsum[k * 8 + d] / gcnt[k];
    }
    if (threadIdx.x < K) sinv[threadIdx.x] = 1.f / gcnt[threadIdx.x];
    __syncthreads();

    float acc = 0.f;

    const int n4 = N >> 2;
    const int4* lab4 = (const int4*)labels;
    const int stride = nblk * 256;

#pragma unroll 2
    for (int i = xi * 256 + threadIdx.x; i < n4; i += stride) {
        int4 L = lab4[i];
        float4 v[D];
#pragma unroll
        for (int d = 0; d < D; d++)
            v[d] = ((const float4*)(pred + (size_t)d * N))[i];

        int ls[4] = {L.x, L.y, L.z, L.w};
#pragma unroll
        for (int e = 0; e < 4; e++) {
            int lab = ls[e];
            float sq = 0.f;
#pragma unroll
            for (int d = 0; d < D; d++) {
                float val = (e == 0) ? v[d].x : (e == 1) ? v[d].y
                           : (e == 2) ? v[d].z : v[d].w;
                float df = sm[lab * D + d] - val;
                sq += df * df;
            }
            float dist = sqrtf(sq);
            float h = fmaxf(dist - DELTA_V, 0.f);
            acc += h * h * sinv[lab];
        }
    }

#pragma unroll
    for (int o = 16; o > 0; o >>= 1)
        acc += __shfl_xor_sync(0xffffffffu, acc, o);

    __shared__ float shv;
    if (threadIdx.x == 0) shv = 0.f;
    __syncthreads();
    if ((threadIdx.x & 31) == 0) atomicAdd(&shv, acc);
    __syncthreads();
    if (threadIdx.x == 0) atomicAdd(gvar, shv);
}

__global__ __launch_bounds__(256, 4) void pass2_kernel(
    const float* __restrict__ binL, const int* __restrict__ binLab,
    const float* __restrict__ instL, const int* __restrict__ instLab, int N,
    float* __restrict__ out) {
    Work w = map_block(blockIdx.x);
    if (w.type == 0) {
        var_impl<2, 2>(binL + (size_t)w.b * 2 * N, binLab + (size_t)w.b * N,
                       N, w.xi, w.nblk, &g_sum[0][w.b][0][0], &g_cnt[0][w.b][0],
                       &g_var2[0][w.b]);
    } else {
        var_impl<5, 6>(instL + (size_t)w.b * 5 * N, instLab + (size_t)w.b * N,
                       N, w.xi, w.nblk, &g_sum[1][w.b][0][0], &g_cnt[1][w.b][0],
                       &g_var2[1][w.b]);
    }

    // ---- last-block finalize ----
    __threadfence();            // release this block's g_var2 atomic
    __syncthreads();
    __shared__ bool is_last;
    if (threadIdx.x == 0) {
        unsigned v = atomicAdd(&g_done, 1u);
        is_last = (v == (unsigned)(TOTAL_BLOCKS - 1));
    }
    __syncthreads();
    if (!is_last) return;
    __threadfence();            // acquire: see all blocks' g_var2/g_sum/g_cnt

    __shared__ float s_res[2];
    if (threadIdx.x < 8) {
        int type = threadIdx.x >> 2, b2 = threadIdx.x & 3;
        int K = type ? 6 : 2, D = type ? 5 : 2;

        float m[6][5];
        for (int k = 0; k < K; k++) {
            float cnt = g_cnt[type][b2][k];
            for (int d = 0; d < D; d++)
                m[k][d] = g_sum[type][b2][k][d] / cnt;
        }
        float l_var = g_var2[type][b2] / (float)K;

        float ld = 0.f;
        for (int i = 0; i < K; i++)
            for (int j = 0; j < K; j++) {
                if (i == j) continue;
                float sq = 0.f;
                for (int d = 0; d < D; d++) {
                    float df = m[i][d] - m[j][d];
                    sq += df * df;
                }
                float dn = fmaxf(TWO_DD - sqrtf(sq), 0.f);
                ld += dn * dn;
            }
        ld /= (float)(K * (K - 1));

        float lr = 0.f;
        for (int k = 0; k < K; k++) {
            float sq = 0.f;
            for (int d = 0; d < D; d++) sq += m[k][d] * m[k][d];
            lr += sqrtf(sq);
        }
        lr /= (float)K;

        float loss = l_var + ld + PREG * lr;
        loss += __shfl_xor_sync(0x000000ffu, loss, 1);
        loss += __shfl_xor_sync(0x000000ffu, loss, 2);
        if ((threadIdx.x & 3) == 0) s_res[type] = loss * 0.25f;
    }
    __syncthreads();
    if (threadIdx.x == 0) {
        out[0] = s_res[0];
        out[1] = s_res[1];
        g_done = 0;
    }
    // re-zero accumulators for the next graph replay
    float* p1 = &g_sum[0][0][0][0];
    for (int i = threadIdx.x; i < 2 * 4 * 8 * 8; i += blockDim.x) p1[i] = 0.f;
    float* p2 = &g_cnt[0][0][0];
    for (int i = threadIdx.x; i < 2 * 4 * 8; i += blockDim.x) p2[i] = 0.f;
    float* p3 = &g_var2[0][0];
    for (int i = threadIdx.x; i < 2 * 4; i += blockDim.x) p3[i] = 0.f;
}

// ---------------------------------------------------------------------------
extern "C" void kernel_launch(void* const* d_in, const int* in_sizes, int n_in,
                              void* d_out, int out_size) {
    const float* binL    = (const float*)d_in[0];
    const int*   binLab  = (const int*)d_in[1];
    const float* instL   = (const float*)d_in[2];
    const int*   instLab = (const int*)d_in[3];
    float* out = (float*)d_out;

    int N = in_sizes[1] / 4;  // B = 4 batches

    pass1_kernel<<<TOTAL_BLOCKS, 256>>>(binL, binLab, instL, instLab, N);
    pass2_kernel<<<TOTAL_BLOCKS, 256>>>(binL, binLab, instL, instLab, N, out);
}

// round 6
// speedup vs baseline: 1.2241x; 1.2241x over previous
#include <cuda_runtime.h>
#include <cuda_bf16.h>
#include <math.h>

// ---------------------------------------------------------------------------
// DiscriminativeLoss: B=4 batches, two losses:
//   binary:   pred [2, N], labels in [0,2)
//   instance: pred [5, N], labels in [0,6)
// out[0] = mean_b binary_loss, out[1] = mean_b instance_loss
// ---------------------------------------------------------------------------

#define DELTA_V   0.5f
#define TWO_DD    6.0f
#define PREG      0.001f

// pass1: 4 blocks/SM (reg-heavy accumulators), balanced by byte ratio 3:6
#define P1_NB_BIN   49
#define P1_NB_INST  99
#define P1_BLOCKS   (4 * (P1_NB_BIN + P1_NB_INST))   // 592

// pass2: 6 blocks/SM (lean), balanced by byte ratio
#define P2_NB_BIN   74
#define P2_NB_INST  148
#define P2_BLOCKS   (4 * (P2_NB_BIN + P2_NB_INST))   // 888

__device__ float    g_sum[2][4][8][8];   // [type][b][k][d]
__device__ float    g_cnt[2][4][8];      // [type][b][k]
__device__ float    g_var2[2][4];        // [type][b]  (inv-count-weighted)
__device__ unsigned g_done;

__device__ __forceinline__ float fsqrt_approx(float x) {
    float r;
    asm("sqrt.approx.f32 %0, %1;" : "=f"(r) : "f"(x));
    return r;
}

struct Work { int type, b, xi, nblk; };
__device__ __forceinline__ Work map_block(int bid, int nb_bin, int nb_inst) {
    Work w;
    if (bid < nb_bin * 4) {
        w.type = 0; w.b = bid / nb_bin; w.xi = bid % nb_bin; w.nblk = nb_bin;
    } else {
        int j = bid - nb_bin * 4;
        w.type = 1; w.b = j / nb_inst; w.xi = j % nb_inst; w.nblk = nb_inst;
    }
    return w;
}

// ---------------------------------------------------------------------------
// Pass 1: segment sums + counts (no unroll pragma — 36 accumulators live)
// ---------------------------------------------------------------------------
template <int D, int K>
__device__ __forceinline__ void reduce_impl(const float* __restrict__ pred,
                                            const int* __restrict__ labels,
                                            int N, int xi, int nblk,
                                            float* __restrict__ gsum,
                                            float* __restrict__ gcnt) {
    float s[K * D];
    float c[K];
#pragma unroll
    for (int i = 0; i < K * D; i++) s[i] = 0.f;
#pragma unroll
    for (int k = 0; k < K; k++) c[k] = 0.f;

    const int n4 = N >> 2;
    const int4* lab4 = (const int4*)labels;
    const int stride = nblk * 256;

    for (int i = xi * 256 + threadIdx.x; i < n4; i += stride) {
        int4 L = lab4[i];
        float4 v[D];
#pragma unroll
        for (int d = 0; d < D; d++)
            v[d] = ((const float4*)(pred + (size_t)d * N))[i];

        int ls[4] = {L.x, L.y, L.z, L.w};
#pragma unroll
        for (int e = 0; e < 4; e++) {
            int lab = ls[e];
#pragma unroll
            for (int k = 0; k < K; k++) {
                float m = (lab == k) ? 1.f : 0.f;
                c[k] += m;
#pragma unroll
                for (int d = 0; d < D; d++) {
                    float val = (e == 0) ? v[d].x : (e == 1) ? v[d].y
                               : (e == 2) ? v[d].z : v[d].w;
                    s[k * D + d] += m * val;
                }
            }
        }
    }

#pragma unroll
    for (int o = 16; o > 0; o >>= 1) {
#pragma unroll
        for (int i = 0; i < K * D; i++) s[i] += __shfl_xor_sync(0xffffffffu, s[i], o);
#pragma unroll
        for (int k = 0; k < K; k++) c[k] += __shfl_xor_sync(0xffffffffu, c[k], o);
    }

    __shared__ float sh[K * D + K];
    for (int i = threadIdx.x; i < K * D + K; i += blockDim.x) sh[i] = 0.f;
    __syncthreads();
    if ((threadIdx.x & 31) == 0) {
#pragma unroll
        for (int i = 0; i < K * D; i++) atomicAdd(&sh[i], s[i]);
#pragma unroll
        for (int k = 0; k < K; k++) atomicAdd(&sh[K * D + k], c[k]);
    }
    __syncthreads();
    if (threadIdx.x < K * D) {
        int k = threadIdx.x / D, d = threadIdx.x % D;
        atomicAdd(&gsum[k * 8 + d], sh[threadIdx.x]);
    }
    if (threadIdx.x < K) atomicAdd(&gcnt[threadIdx.x], sh[K * D + threadIdx.x]);
}

__global__ __launch_bounds__(256, 4) void pass1_kernel(
    const float* __restrict__ binL, const int* __restrict__ binLab,
    const float* __restrict__ instL, const int* __restrict__ instLab, int N) {
    Work w = map_block(blockIdx.x, P1_NB_BIN, P1_NB_INST);
    if (w.type == 0) {
        reduce_impl<2, 2>(binL + (size_t)w.b * 2 * N, binLab + (size_t)w.b * N,
                          N, w.xi, w.nblk, &g_sum[0][w.b][0][0], &g_cnt[0][w.b][0]);
    } else {
        reduce_impl<5, 6>(instL + (size_t)w.b * 5 * N, instLab + (size_t)w.b * N,
                          N, w.xi, w.nblk, &g_sum[1][w.b][0][0], &g_cnt[1][w.b][0]);
    }
}

// ---------------------------------------------------------------------------
// Pass 2: lean (single accumulator, approx sqrt), 6 blocks/SM.
// UNROLL=1 for instance (register budget), 2 for binary.
// ---------------------------------------------------------------------------
template <int D, int K, int UNROLL>
__device__ __forceinline__ void var_impl(const float* __restrict__ pred,
                                         const int* __restrict__ labels,
                                         int N, int xi, int nblk,
                                         const float* __restrict__ gsum,
                                         const float* __restrict__ gcnt,
                                         float* __restrict__ gvar) {
    __shared__ float sm[K * D];
    __shared__ float sinv[K];
    if (threadIdx.x < K * D) {
        int k = threadIdx.x / D, d = threadIdx.x % D;
        sm[threadIdx.x] = gsum[k * 8 + d] / gcnt[k];
    }
    if (threadIdx.x < K) sinv[threadIdx.x] = 1.f / gcnt[threadIdx.x];
    __syncthreads();

    float acc = 0.f;

    const int n4 = N >> 2;
    const int4* lab4 = (const int4*)labels;
    const int stride = nblk * 256;

#pragma unroll UNROLL
    for (int i = xi * 256 + threadIdx.x; i < n4; i += stride) {
        int4 L = lab4[i];
        float4 v[D];
#pragma unroll
        for (int d = 0; d < D; d++)
            v[d] = ((const float4*)(pred + (size_t)d * N))[i];

        int ls[4] = {L.x, L.y, L.z, L.w};
#pragma unroll
        for (int e = 0; e < 4; e++) {
            int lab = ls[e];
            float sq = 0.f;
#pragma unroll
            for (int d = 0; d < D; d++) {
                float val = (e == 0) ? v[d].x : (e == 1) ? v[d].y
                           : (e == 2) ? v[d].z : v[d].w;
                float df = sm[lab * D + d] - val;
                sq += df * df;
            }
            float dist = fsqrt_approx(sq);
            float h = fmaxf(dist - DELTA_V, 0.f);
            acc += h * h * sinv[lab];
        }
    }

#pragma unroll
    for (int o = 16; o > 0; o >>= 1)
        acc += __shfl_xor_sync(0xffffffffu, acc, o);

    __shared__ float shv;
    if (threadIdx.x == 0) shv = 0.f;
    __syncthreads();
    if ((threadIdx.x & 31) == 0) atomicAdd(&shv, acc);
    __syncthreads();
    if (threadIdx.x == 0) atomicAdd(gvar, shv);
}

__global__ __launch_bounds__(256, 6) void pass2_kernel(
    const float* __restrict__ binL, const int* __restrict__ binLab,
    const float* __restrict__ instL, const int* __restrict__ instLab, int N,
    float* __restrict__ out) {
    Work w = map_block(blockIdx.x, P2_NB_BIN, P2_NB_INST);
    if (w.type == 0) {
        var_impl<2, 2, 2>(binL + (size_t)w.b * 2 * N, binLab + (size_t)w.b * N,
                          N, w.xi, w.nblk, &g_sum[0][w.b][0][0], &g_cnt[0][w.b][0],
                          &g_var2[0][w.b]);
    } else {
        var_impl<5, 6, 1>(instL + (size_t)w.b * 5 * N, instLab + (size_t)w.b * N,
                          N, w.xi, w.nblk, &g_sum[1][w.b][0][0], &g_cnt[1][w.b][0],
                          &g_var2[1][w.b]);
    }

    // ---- last-block finalize ----
    __threadfence();
    __syncthreads();
    __shared__ bool is_last;
    if (threadIdx.x == 0) {
        unsigned v = atomicAdd(&g_done, 1u);
        is_last = (v == (unsigned)(P2_BLOCKS - 1));
    }
    __syncthreads();
    if (!is_last) return;
    __threadfence();

    __shared__ float s_res[2];
    if (threadIdx.x < 8) {
        int type = threadIdx.x >> 2, b2 = threadIdx.x & 3;
        int K = type ? 6 : 2, D = type ? 5 : 2;

        float m[6][5];
        for (int k = 0; k < K; k++) {
            float cnt = g_cnt[type][b2][k];
            for (int d = 0; d < D; d++)
                m[k][d] = g_sum[type][b2][k][d] / cnt;
        }
        float l_var = g_var2[type][b2] / (float)K;

        float ld = 0.f;
        for (int i = 0; i < K; i++)
            for (int j = 0; j < K; j++) {
                if (i == j) continue;
                float sq = 0.f;
                for (int d = 0; d < D; d++) {
                    float df = m[i][d] - m[j][d];
                    sq += df * df;
                }
                float dn = fmaxf(TWO_DD - sqrtf(sq), 0.f);
                ld += dn * dn;
            }
        ld /= (float)(K * (K - 1));

        float lr = 0.f;
        for (int k = 0; k < K; k++) {
            float sq = 0.f;
            for (int d = 0; d < D; d++) sq += m[k][d] * m[k][d];
            lr += sqrtf(sq);
        }
        lr /= (float)K;

        float loss = l_var + ld + PREG * lr;
        loss += __shfl_xor_sync(0x000000ffu, loss, 1);
        loss += __shfl_xor_sync(0x000000ffu, loss, 2);
        if ((threadIdx.x & 3) == 0) s_res[type] = loss * 0.25f;
    }
    __syncthreads();
    if (threadIdx.x == 0) {
        out[0] = s_res[0];
        out[1] = s_res[1];
        g_done = 0;
    }
    float* p1 = &g_sum[0][0][0][0];
    for (int i = threadIdx.x; i < 2 * 4 * 8 * 8; i += blockDim.x) p1[i] = 0.f;
    float* p2 = &g_cnt[0][0][0];
    for (int i = threadIdx.x; i < 2 * 4 * 8; i += blockDim.x) p2[i] = 0.f;
    float* p3 = &g_var2[0][0];
    for (int i = threadIdx.x; i < 2 * 4; i += blockDim.x) p3[i] = 0.f;
}

// ---------------------------------------------------------------------------
extern "C" void kernel_launch(void* const* d_in, const int* in_sizes, int n_in,
                              void* d_out, int out_size) {
    const float* binL    = (const float*)d_in[0];
    const int*   binLab  = (const int*)d_in[1];
    const float* instL   = (const float*)d_in[2];
    const int*   instLab = (const int*)d_in[3];
    float* out = (float*)d_out;

    int N = in_sizes[1] / 4;  // B = 4 batches

    pass1_kernel<<<P1_BLOCKS, 256>>>(binL, binLab, instL, instLab, N);
    pass2_kernel<<<P2_BLOCKS, 256>>>(binL, binLab, instL, instLab, N, out);
}